// round 11
// baseline (speedup 1.0000x reference)
#include <cuda_runtime.h>
#include <cstdint>

#define NROWS 8000
#define NDIM  9
#define NBLK  148            // one block per SM, wave-1 co-resident
#define NTHR  1024
#define RPT   8              // rows per thread in scan (1024*8 = 8192 >= 8000)
#define N8    (NROWS / 8)    // 1000 32-byte chunks per row
#define WROWS 8
#define NGRP  (NROWS / WROWS)                     // 1000 groups of 8 rows
#define SMEM_BYTES (NROWS * (int)sizeof(float))   // w1_bar only: 32000 B

// Scratch (device globals — no allocation allowed in kernel_launch)
__device__ unsigned long long g_bar = 0ULL;   // monotonic grid barrier counter
__device__ __align__(16) float g_s1[NROWS];
__device__ __align__(16) float g_s2[NROWS];
__device__ __align__(16) float g_f1[NROWS];
__device__ __align__(16) float g_f2[NROWS];

__global__ __launch_bounds__(NTHR, 1)
void anfis_fused_kernel(const float* __restrict__ x,
                        const float* __restrict__ a1, const float* __restrict__ c1,
                        const float* __restrict__ a2, const float* __restrict__ c2,
                        const float* __restrict__ w_fc1, const float* __restrict__ b_fc1,
                        const float* __restrict__ w_fc2, const float* __restrict__ b_fc2,
                        float* __restrict__ out)
{
    extern __shared__ float sw1[];        // [NROWS] w1_bar
    __shared__ float2 sh[32];

    const int tid  = threadIdx.x;
    const int lane = tid & 31;
    const int warp = tid >> 5;

    // ---------------- Phase A: per-row sums + fc outputs (grid-parallel) ----
    {
        const int row = blockIdx.x * NTHR + tid;
        if (row < NROWS) {
            const float ia1 = 1.0f / a1[0], cc1 = c1[0];
            const float ia2 = 1.0f / a2[0], cc2 = c2[0];
            float acc1 = 0.0f, acc2 = 0.0f;
            float ff1 = b_fc1[0], ff2 = b_fc2[0];
#pragma unroll
            for (int d = 0; d < NDIM; d++) {
                const float xv = __ldg(&x[row * NDIM + d]);
                const float t1 = (xv - cc1) * ia1;
                const float t2 = (xv - cc2) * ia2;
                acc1 = fmaf(t1, t1, acc1);
                acc2 = fmaf(t2, t2, acc2);
                ff1  = fmaf(xv, __ldg(&w_fc1[d]), ff1);
                ff2  = fmaf(xv, __ldg(&w_fc2[d]), ff2);
            }
            g_s1[row] = acc1;
            g_s2[row] = acc2;
            g_f1[row] = ff1;
            g_f2[row] = ff2;
        }
    }

    // ---------------- Grid barrier (monotonic counter, replay-safe) ---------
    __syncthreads();
    if (tid == 0) {
        __threadfence();
        const unsigned long long my = atomicAdd(&g_bar, 1ULL) + 1ULL;
        const unsigned long long target = ((my + (NBLK - 1ULL)) / NBLK) * NBLK;
        volatile unsigned long long* p = &g_bar;
        while (*p < target) { }
        __threadfence();
    }
    __syncthreads();

    // ---------------- Phase B: redundant scan -> w1_bar into smem -----------
    {
        const int base = tid * RPT;
        float ls1[RPT], ls2[RPT];
        float run1 = 0.0f, run2 = 0.0f;
#pragma unroll
        for (int r = 0; r < RPT; r++) {
            const int row = base + r;
            if (row < NROWS) {
                run1 += g_s1[row];
                run2 += g_s2[row];
            }
            ls1[r] = run1;
            ls2[r] = run2;
        }

        float inc1 = run1, inc2 = run2;
#pragma unroll
        for (int o = 1; o < 32; o <<= 1) {
            const float n1 = __shfl_up_sync(0xffffffffu, inc1, o);
            const float n2 = __shfl_up_sync(0xffffffffu, inc2, o);
            if (lane >= o) { inc1 += n1; inc2 += n2; }
        }
        if (lane == 31) sh[warp] = make_float2(inc1, inc2);
        __syncthreads();
        if (warp == 0) {
            const float2 v = sh[lane];
            float a = v.x, b = v.y;
#pragma unroll
            for (int o = 1; o < 32; o <<= 1) {
                const float n1 = __shfl_up_sync(0xffffffffu, a, o);
                const float n2 = __shfl_up_sync(0xffffffffu, b, o);
                if (lane >= o) { a += n1; b += n2; }
            }
            sh[lane] = make_float2(a - v.x, b - v.y);  // exclusive prefix
        }
        __syncthreads();

        const float ex1 = sh[warp].x + (inc1 - run1);
        const float ex2 = sh[warp].y + (inc2 - run2);

#pragma unroll
        for (int r = 0; r < RPT; r++) {
            const int row = base + r;
            if (row < NROWS) {
                const float w1v = expf(-(ex1 + ls1[r]));
                const float w2v = expf(-(ex2 + ls2[r]));
                sw1[row] = w1v / (w1v + w2v);   // w1_bar; w2_bar = 1 - w1_bar
            }
        }
    }
    __syncthreads();

    // ---------------- Phase C: 256 MB streaming write, 256-bit stores -------
    // out[i][j] = f2[i] + (f1[i]-f2[i]) * w1_bar[j].
    // Each thread owns one 32-byte chunk (8 floats) across 8 rows per group.
    {
        const float4* w4 = reinterpret_cast<const float4*>(sw1);

        for (int g = blockIdx.x; g < NGRP; g += NBLK) {
            const int i0 = g * WROWS;
            float f2r[WROWS], dr[WROWS];
#pragma unroll
            for (int r = 0; r < WROWS; r++) {
                const float f2v = g_f2[i0 + r];
                f2r[r] = f2v;
                dr[r]  = g_f1[i0 + r] - f2v;
            }
            for (int j = tid; j < N8; j += NTHR) {
                const float4 a0 = w4[2 * j];
                const float4 a1v = w4[2 * j + 1];
#pragma unroll
                for (int r = 0; r < WROWS; r++) {
                    const float d  = dr[r];
                    const float f2 = f2r[r];
                    const float o0 = fmaf(d, a0.x, f2);
                    const float o1 = fmaf(d, a0.y, f2);
                    const float o2 = fmaf(d, a0.z, f2);
                    const float o3 = fmaf(d, a0.w, f2);
                    const float o4 = fmaf(d, a1v.x, f2);
                    const float o5 = fmaf(d, a1v.y, f2);
                    const float o6 = fmaf(d, a1v.z, f2);
                    const float o7 = fmaf(d, a1v.w, f2);
                    float* p = out + (size_t)(i0 + r) * NROWS + (size_t)j * 8;
                    asm volatile(
                        "st.global.v8.f32 [%0], {%1, %2, %3, %4, %5, %6, %7, %8};"
                        :: "l"(p), "f"(o0), "f"(o1), "f"(o2), "f"(o3),
                           "f"(o4), "f"(o5), "f"(o6), "f"(o7) : "memory");
                }
            }
        }
    }
}

// ---------------------------------------------------------------------------
extern "C" void kernel_launch(void* const* d_in, const int* in_sizes, int n_in,
                              void* d_out, int out_size)
{
    const float* x     = (const float*)d_in[0];
    const float* a1    = (const float*)d_in[1];
    const float* c1    = (const float*)d_in[2];
    const float* a2    = (const float*)d_in[3];
    const float* c2    = (const float*)d_in[4];
    const float* w_fc1 = (const float*)d_in[5];
    const float* b_fc1 = (const float*)d_in[6];
    const float* w_fc2 = (const float*)d_in[7];
    const float* b_fc2 = (const float*)d_in[8];
    float* out = (float*)d_out;

    cudaFuncSetAttribute(anfis_fused_kernel,
                         cudaFuncAttributeMaxDynamicSharedMemorySize, SMEM_BYTES);
    anfis_fused_kernel<<<NBLK, NTHR, SMEM_BYTES>>>(x, a1, c1, a2, c2,
                                                   w_fc1, b_fc1, w_fc2, b_fc2, out);
}

// round 14
// speedup vs baseline: 1.0050x; 1.0050x over previous
#include <cuda_runtime.h>
#include <cstdint>

#define NROWS 8000
#define NDIM  9
#define NBLK  148            // one block per SM, wave-1 co-resident
#define NTHR  1024
#define RPT   8              // rows per thread in scan (1024*8 = 8192 >= 8000)
#define N4    (NROWS / 4)    // 2000 float4 per row
#define WROWS 8
#define NGRP  (NROWS / WROWS)                     // 1000 groups of 8 rows
#define SMEM_BYTES (NROWS * (int)sizeof(float))   // w1_bar only: 32000 B

// Scratch (device globals — no allocation allowed in kernel_launch)
__device__ unsigned long long g_bar = 0ULL;   // monotonic grid barrier counter
__device__ __align__(16) float g_s1[NROWS];
__device__ __align__(16) float g_s2[NROWS];
__device__ __align__(16) float g_f1[NROWS];
__device__ __align__(16) float g_f2[NROWS];

__global__ __launch_bounds__(NTHR, 1)
void anfis_fused_kernel(const float* __restrict__ x,
                        const float* __restrict__ a1, const float* __restrict__ c1,
                        const float* __restrict__ a2, const float* __restrict__ c2,
                        const float* __restrict__ w_fc1, const float* __restrict__ b_fc1,
                        const float* __restrict__ w_fc2, const float* __restrict__ b_fc2,
                        float* __restrict__ out)
{
    extern __shared__ float sw1[];        // [NROWS] w1_bar
    __shared__ float2 sh[32];

    const int tid  = threadIdx.x;
    const int lane = tid & 31;
    const int warp = tid >> 5;

    // ---------------- Phase A: per-row sums + fc outputs (grid-parallel) ----
    {
        const int row = blockIdx.x * NTHR + tid;
        if (row < NROWS) {
            const float ia1 = 1.0f / a1[0], cc1 = c1[0];
            const float ia2 = 1.0f / a2[0], cc2 = c2[0];
            float acc1 = 0.0f, acc2 = 0.0f;
            float ff1 = b_fc1[0], ff2 = b_fc2[0];
#pragma unroll
            for (int d = 0; d < NDIM; d++) {
                const float xv = __ldg(&x[row * NDIM + d]);
                const float t1 = (xv - cc1) * ia1;
                const float t2 = (xv - cc2) * ia2;
                acc1 = fmaf(t1, t1, acc1);
                acc2 = fmaf(t2, t2, acc2);
                ff1  = fmaf(xv, __ldg(&w_fc1[d]), ff1);
                ff2  = fmaf(xv, __ldg(&w_fc2[d]), ff2);
            }
            g_s1[row] = acc1;
            g_s2[row] = acc2;
            g_f1[row] = ff1;
            g_f2[row] = ff2;
        }
    }

    // ---------------- Grid barrier (monotonic counter, replay-safe) ---------
    __syncthreads();
    if (tid == 0) {
        __threadfence();
        const unsigned long long my = atomicAdd(&g_bar, 1ULL) + 1ULL;
        const unsigned long long target = ((my + (NBLK - 1ULL)) / NBLK) * NBLK;
        volatile unsigned long long* p = &g_bar;
        while (*p < target) { }
        __threadfence();
    }
    __syncthreads();

    // ---------------- Phase B: redundant scan -> w1_bar into smem -----------
    {
        const int base = tid * RPT;
        float ls1[RPT], ls2[RPT];
        float run1 = 0.0f, run2 = 0.0f;
#pragma unroll
        for (int r = 0; r < RPT; r++) {
            const int row = base + r;
            if (row < NROWS) {
                run1 += g_s1[row];
                run2 += g_s2[row];
            }
            ls1[r] = run1;
            ls2[r] = run2;
        }

        float inc1 = run1, inc2 = run2;
#pragma unroll
        for (int o = 1; o < 32; o <<= 1) {
            const float n1 = __shfl_up_sync(0xffffffffu, inc1, o);
            const float n2 = __shfl_up_sync(0xffffffffu, inc2, o);
            if (lane >= o) { inc1 += n1; inc2 += n2; }
        }
        if (lane == 31) sh[warp] = make_float2(inc1, inc2);
        __syncthreads();
        if (warp == 0) {
            const float2 v = sh[lane];
            float a = v.x, b = v.y;
#pragma unroll
            for (int o = 1; o < 32; o <<= 1) {
                const float n1 = __shfl_up_sync(0xffffffffu, a, o);
                const float n2 = __shfl_up_sync(0xffffffffu, b, o);
                if (lane >= o) { a += n1; b += n2; }
            }
            sh[lane] = make_float2(a - v.x, b - v.y);  // exclusive prefix
        }
        __syncthreads();

        const float ex1 = sh[warp].x + (inc1 - run1);
        const float ex2 = sh[warp].y + (inc2 - run2);

#pragma unroll
        for (int r = 0; r < RPT; r++) {
            const int row = base + r;
            if (row < NROWS) {
                const float w1v = expf(-(ex1 + ls1[r]));
                const float w2v = expf(-(ex2 + ls2[r]));
                sw1[row] = w1v / (w1v + w2v);   // w1_bar; w2_bar = 1 - w1_bar
            }
        }
    }
    __syncthreads();

    // ---------------- Phase C: 256 MB streaming write -----------------------
    // out[i][j] = f2[i] + (f1[i]-f2[i]) * w1_bar[j]; one smem read per 16B out.
    // Period is pinned at 256 MB / ~4.95 TB/s HBM write-drain (machine floor).
    {
        const float4* w4 = reinterpret_cast<const float4*>(sw1);
        float4* out4 = reinterpret_cast<float4*>(out);

        for (int g = blockIdx.x; g < NGRP; g += NBLK) {
            const int i0 = g * WROWS;
            float f2r[WROWS], dr[WROWS];
#pragma unroll
            for (int r = 0; r < WROWS; r++) {
                const float f2v = g_f2[i0 + r];
                f2r[r] = f2v;
                dr[r]  = g_f1[i0 + r] - f2v;
            }
            for (int j = tid; j < N4; j += NTHR) {
                const float4 a = w4[j];
#pragma unroll
                for (int r = 0; r < WROWS; r++) {
                    float4 o;
                    o.x = fmaf(dr[r], a.x, f2r[r]);
                    o.y = fmaf(dr[r], a.y, f2r[r]);
                    o.z = fmaf(dr[r], a.z, f2r[r]);
                    o.w = fmaf(dr[r], a.w, f2r[r]);
                    out4[(size_t)(i0 + r) * N4 + j] = o;
                }
            }
        }
    }
}

// ---------------------------------------------------------------------------
extern "C" void kernel_launch(void* const* d_in, const int* in_sizes, int n_in,
                              void* d_out, int out_size)
{
    const float* x     = (const float*)d_in[0];
    const float* a1    = (const float*)d_in[1];
    const float* c1    = (const float*)d_in[2];
    const float* a2    = (const float*)d_in[3];
    const float* c2    = (const float*)d_in[4];
    const float* w_fc1 = (const float*)d_in[5];
    const float* b_fc1 = (const float*)d_in[6];
    const float* w_fc2 = (const float*)d_in[7];
    const float* b_fc2 = (const float*)d_in[8];
    float* out = (float*)d_out;

    cudaFuncSetAttribute(anfis_fused_kernel,
                         cudaFuncAttributeMaxDynamicSharedMemorySize, SMEM_BYTES);
    anfis_fused_kernel<<<NBLK, NTHR, SMEM_BYTES>>>(x, a1, c1, a2, c2,
                                                   w_fc1, b_fc1, w_fc2, b_fc2, out);
}